// round 2
// baseline (speedup 1.0000x reference)
#include <cuda_runtime.h>
#include <math.h>

#define NN 10000
#define EE 160000
#define FF 256
#define RR 20
#define TE 64

// ---------------- scratch (device globals; no runtime allocation) ----------------
__device__ float g_P0[NN * FF];
__device__ float g_P1[NN * FF];
__device__ float g_sum[NN * FF];
__device__ float g_sumsq[NN * FF];
__device__ float g_minb[NN * FF];
__device__ float g_maxb[NN * FF];
__device__ float g_deg[NN];
__device__ float g_avglog;
__device__ float g_agg[NN * 12 * FF];

// ---------------- helpers ----------------
__device__ __forceinline__ void red_add_v4(float* p, float a, float b, float c, float d) {
    asm volatile("red.global.add.v4.f32 [%0], {%1,%2,%3,%4};"
                 :: "l"(p), "f"(a), "f"(b), "f"(c), "f"(d) : "memory");
}
__device__ __forceinline__ void atomicMaxF(float* p, float v) {
    if (v >= 0.f) atomicMax((int*)p, __float_as_int(v));
    else          atomicMin((unsigned int*)p, __float_as_uint(v));
}
__device__ __forceinline__ void atomicMinF(float* p, float v) {
    if (v >= 0.f) atomicMin((int*)p, __float_as_int(v));
    else          atomicMax((unsigned int*)p, __float_as_uint(v));
}

// ---------------- init ----------------
__global__ void init_kernel() {
    int i = blockIdx.x * 256 + threadIdx.x;
    if (i < NN * FF) {
        g_sum[i]   = 0.f;
        g_sumsq[i] = 0.f;
        g_minb[i]  = __int_as_float(0x7f800000);   // +inf
        g_maxb[i]  = __int_as_float(0xff800000);   // -inf
        if (i < NN) g_deg[i] = 0.f;
    }
}

// ---------------- node precompute: P0 = x@Wpre[0:256], P1 = x@Wpre[256:512] ----------------
__global__ __launch_bounds__(256) void gemm_pre_kernel(const float* __restrict__ x,
                                                       const float* __restrict__ Wpre) {
    __shared__ float sA[64 * 16];
    __shared__ float sW[16 * 256];
    const float* W = Wpre + blockIdx.y * FF * FF;
    float* P = blockIdx.y ? g_P1 : g_P0;
    int tid = threadIdx.x, ty = tid >> 5, tx = tid & 31;
    int n0 = blockIdx.x * 64;
    float acc[8][8];
#pragma unroll
    for (int i = 0; i < 8; i++)
#pragma unroll
        for (int j = 0; j < 8; j++) acc[i][j] = 0.f;

    for (int k0 = 0; k0 < FF; k0 += 16) {
        {
            int vrow = tid >> 2, c4 = tid & 3;
            int n = n0 + vrow;
            float4 av = make_float4(0.f, 0.f, 0.f, 0.f);
            if (n < NN) av = *(const float4*)&x[n * FF + k0 + c4 * 4];
            *(float4*)&sA[vrow * 16 + c4 * 4] = av;
        }
#pragma unroll
        for (int q = 0; q < 4; q++) {
            int v = q * 256 + tid, row = v >> 6, c4 = v & 63;
            *(float4*)&sW[row * 256 + c4 * 4] = *(const float4*)&W[(k0 + row) * FF + c4 * 4];
        }
        __syncthreads();
#pragma unroll
        for (int kk4 = 0; kk4 < 4; kk4++) {
            float4 a4[8];
#pragma unroll
            for (int i = 0; i < 8; i++) a4[i] = *(const float4*)&sA[(ty * 8 + i) * 16 + kk4 * 4];
#pragma unroll
            for (int u = 0; u < 4; u++) {
                const float* wr = &sW[(kk4 * 4 + u) * 256 + tx * 8];
                float4 b0 = *(const float4*)wr, b1 = *(const float4*)(wr + 4);
                float bb[8] = {b0.x, b0.y, b0.z, b0.w, b1.x, b1.y, b1.z, b1.w};
#pragma unroll
                for (int i = 0; i < 8; i++) {
                    float a = (u == 0) ? a4[i].x : (u == 1) ? a4[i].y : (u == 2) ? a4[i].z : a4[i].w;
#pragma unroll
                    for (int j = 0; j < 8; j++) acc[i][j] = fmaf(a, bb[j], acc[i][j]);
                }
            }
        }
        __syncthreads();
    }
#pragma unroll
    for (int i = 0; i < 8; i++) {
        int n = n0 + ty * 8 + i;
        if (n < NN) {
#pragma unroll
            for (int j = 0; j < 8; j++) P[n * FF + tx * 8 + j] = acc[i][j];
        }
    }
}

// ---------------- fused edge pipeline ----------------
// smem layout (floats): sA[64*264], sM[64*264], sW[16*256], sRbf[64*20], sEv[192], idx[128 ints]
#define EDGE_SMEM_BYTES ((64 * 264 * 2 + 16 * 256 + 64 * RR + 192) * 4 + 128 * 4)

__device__ __forceinline__ void tile_gemm256(const float* src, const float* __restrict__ Wg,
                                             int wstride, float* sW, int tid, int ty, int tx,
                                             float acc[8][8]) {
#pragma unroll
    for (int i = 0; i < 8; i++)
#pragma unroll
        for (int j = 0; j < 8; j++) acc[i][j] = 0.f;
    for (int k0 = 0; k0 < FF; k0 += 16) {
#pragma unroll
        for (int q = 0; q < 4; q++) {
            int v = q * 256 + tid, row = v >> 6, c4 = v & 63;
            *(float4*)&sW[row * 256 + c4 * 4] = *(const float4*)&Wg[(k0 + row) * wstride + c4 * 4];
        }
        __syncthreads();
#pragma unroll
        for (int kk4 = 0; kk4 < 4; kk4++) {
            float4 a4[8];
#pragma unroll
            for (int i = 0; i < 8; i++)
                a4[i] = *(const float4*)&src[(ty * 8 + i) * 264 + k0 + kk4 * 4];
#pragma unroll
            for (int u = 0; u < 4; u++) {
                const float* wr = &sW[(kk4 * 4 + u) * 256 + tx * 8];
                float4 b0 = *(const float4*)wr, b1 = *(const float4*)(wr + 4);
                float bb[8] = {b0.x, b0.y, b0.z, b0.w, b1.x, b1.y, b1.z, b1.w};
#pragma unroll
                for (int i = 0; i < 8; i++) {
                    float a = (u == 0) ? a4[i].x : (u == 1) ? a4[i].y : (u == 2) ? a4[i].z : a4[i].w;
#pragma unroll
                    for (int j = 0; j < 8; j++) acc[i][j] = fmaf(a, bb[j], acc[i][j]);
                }
            }
        }
        __syncthreads();
    }
}

__device__ __forceinline__ void compute_frbf(const float* sRbf, int e,
                                             const float* __restrict__ Wlin, int gcol,
                                             float ff[8]) {
    float4 f0 = make_float4(0.f, 0.f, 0.f, 0.f);
    float4 f1 = make_float4(0.f, 0.f, 0.f, 0.f);
#pragma unroll
    for (int k = 0; k < RR; k++) {
        float rb = sRbf[e * RR + k];
        const float* w = &Wlin[k * 768 + gcol];
        float4 w0 = *(const float4*)w, w1 = *(const float4*)(w + 4);
        f0.x = fmaf(rb, w0.x, f0.x); f0.y = fmaf(rb, w0.y, f0.y);
        f0.z = fmaf(rb, w0.z, f0.z); f0.w = fmaf(rb, w0.w, f0.w);
        f1.x = fmaf(rb, w1.x, f1.x); f1.y = fmaf(rb, w1.y, f1.y);
        f1.z = fmaf(rb, w1.z, f1.z); f1.w = fmaf(rb, w1.w, f1.w);
    }
    ff[0] = f0.x; ff[1] = f0.y; ff[2] = f0.z; ff[3] = f0.w;
    ff[4] = f1.x; ff[5] = f1.y; ff[6] = f1.z; ff[7] = f1.w;
}

__global__ __launch_bounds__(256) void edge_kernel(
    const float* __restrict__ x, const float* __restrict__ edge_rbf,
    const float* __restrict__ edge_vec,
    const float* __restrict__ Wemb, const float* __restrict__ bemb,
    const float* __restrict__ Wpre2, const float* __restrict__ bpre,
    const float* __restrict__ Ws1, const float* __restrict__ bs1,
    const float* __restrict__ Ws2, const float* __restrict__ bs2,
    const float* __restrict__ Wlin, const int* __restrict__ eidx,
    float* __restrict__ out_v) {
    extern __shared__ float sm[];
    float* sA   = sm;
    float* sM   = sA + 64 * 264;
    float* sW   = sM + 64 * 264;
    float* sRbf = sW + 16 * 256;
    float* sEv  = sRbf + 64 * RR;
    int* sSrc = (int*)(sEv + 192);
    int* sDst = sSrc + 64;

    int tid = threadIdx.x, ty = tid >> 5, tx = tid & 31;
    int e0 = blockIdx.x * TE;

    if (tid < TE) {
        int s = eidx[e0 + tid], d = eidx[EE + e0 + tid];
        sSrc[tid] = s; sDst[tid] = d;
        atomicAdd(&g_deg[d], 1.0f);
    }
    for (int i = tid; i < TE * RR; i += 256) sRbf[i] = edge_rbf[e0 * RR + i];
    if (tid < TE * 3) sEv[tid] = edge_vec[e0 * 3 + tid];
    __syncthreads();

    float acc[8][8];

    // ---- 1) r = relu(rbf @ Wemb + bemb) -> sA ----
#pragma unroll
    for (int i = 0; i < 8; i++)
#pragma unroll
        for (int j = 0; j < 8; j++) acc[i][j] = 0.f;
#pragma unroll
    for (int k = 0; k < RR; k++) {
        const float* w = &Wemb[k * FF + tx * 8];
        float4 w0 = *(const float4*)w, w1 = *(const float4*)(w + 4);
        float bb[8] = {w0.x, w0.y, w0.z, w0.w, w1.x, w1.y, w1.z, w1.w};
#pragma unroll
        for (int i = 0; i < 8; i++) {
            float a = sRbf[(ty * 8 + i) * RR + k];
#pragma unroll
            for (int j = 0; j < 8; j++) acc[i][j] = fmaf(a, bb[j], acc[i][j]);
        }
    }
    {
        const float* bp = &bemb[tx * 8];
        float4 b0 = *(const float4*)bp, b1 = *(const float4*)(bp + 4);
        float bb[8] = {b0.x, b0.y, b0.z, b0.w, b1.x, b1.y, b1.z, b1.w};
#pragma unroll
        for (int i = 0; i < 8; i++) {
            int e = ty * 8 + i;
#pragma unroll
            for (int j = 0; j < 8; j++)
                sA[e * 264 + tx * 8 + j] = fmaxf(acc[i][j] + bb[j], 0.f);
        }
    }
    __syncthreads();

    // ---- 2) m = r @ Wpre2 + P0[src] + P1[dst] + bpre -> sM ----
    tile_gemm256(sA, Wpre2, FF, sW, tid, ty, tx, acc);
    {
        const float* bp = &bpre[tx * 8];
        float4 b0 = *(const float4*)bp, b1 = *(const float4*)(bp + 4);
        float bb[8] = {b0.x, b0.y, b0.z, b0.w, b1.x, b1.y, b1.z, b1.w};
#pragma unroll
        for (int i = 0; i < 8; i++) {
            int e = ty * 8 + i;
            int s = sSrc[e], d = sDst[e];
            const float* p0 = &g_P0[s * FF + tx * 8];
            const float* p1 = &g_P1[d * FF + tx * 8];
            float4 p00 = *(const float4*)p0, p01 = *(const float4*)(p0 + 4);
            float4 p10 = *(const float4*)p1, p11 = *(const float4*)(p1 + 4);
            float q0[8] = {p00.x, p00.y, p00.z, p00.w, p01.x, p01.y, p01.z, p01.w};
            float q1[8] = {p10.x, p10.y, p10.z, p10.w, p11.x, p11.y, p11.z, p11.w};
#pragma unroll
            for (int j = 0; j < 8; j++)
                sM[e * 264 + tx * 8 + j] = acc[i][j] + bb[j] + q0[j] + q1[j];
        }
    }

    // ---- 3) t = silu(m @ Ws1 + bs1) -> sA ----
    tile_gemm256(sM, Ws1, FF, sW, tid, ty, tx, acc);
    {
        const float* bp = &bs1[tx * 8];
        float4 b0 = *(const float4*)bp, b1 = *(const float4*)(bp + 4);
        float bb[8] = {b0.x, b0.y, b0.z, b0.w, b1.x, b1.y, b1.z, b1.w};
#pragma unroll
        for (int i = 0; i < 8; i++) {
            int e = ty * 8 + i;
#pragma unroll
            for (int j = 0; j < 8; j++) {
                float mv = acc[i][j] + bb[j];
                sA[e * 264 + tx * 8 + j] = __fdividef(mv, 1.f + __expf(-mv));
            }
        }
    }

    // ---- 4a) chunk 0: g_state -> sM ----
    tile_gemm256(sA, Ws2 + 0, 768, sW, tid, ty, tx, acc);
    {
        const float* bp = &bs2[0 + tx * 8];
        float4 b0 = *(const float4*)bp, b1 = *(const float4*)(bp + 4);
        float bb[8] = {b0.x, b0.y, b0.z, b0.w, b1.x, b1.y, b1.z, b1.w};
#pragma unroll
        for (int i = 0; i < 8; i++) {
            int e = ty * 8 + i;
            float ff[8]; compute_frbf(sRbf, e, Wlin, 0 + tx * 8, ff);
#pragma unroll
            for (int j = 0; j < 8; j++)
                sM[e * 264 + tx * 8 + j] = (acc[i][j] + bb[j]) * ff[j];
        }
    }

    // ---- 4b) chunk 1: g_edge, scatter mv into out_v ----
    tile_gemm256(sA, Ws2 + 256, 768, sW, tid, ty, tx, acc);
    {
        const float* bp = &bs2[256 + tx * 8];
        float4 b0 = *(const float4*)bp, b1 = *(const float4*)(bp + 4);
        float bb[8] = {b0.x, b0.y, b0.z, b0.w, b1.x, b1.y, b1.z, b1.w};
#pragma unroll
        for (int i = 0; i < 8; i++) {
            int e = ty * 8 + i;
            int d = sDst[e];
            float ff[8]; compute_frbf(sRbf, e, Wlin, 256 + tx * 8, ff);
            float ge[8];
#pragma unroll
            for (int j = 0; j < 8; j++) ge[j] = (acc[i][j] + bb[j]) * ff[j];
            const float* xp = &x[d * FF + tx * 8];
            float4 x0 = *(const float4*)xp, x1 = *(const float4*)(xp + 4);
            float xd[8] = {x0.x, x0.y, x0.z, x0.w, x1.x, x1.y, x1.z, x1.w};
            float gs[8];
#pragma unroll
            for (int j = 0; j < 8; j++) gs[j] = sM[e * 264 + tx * 8 + j];
            float ev0 = sEv[e * 3 + 0], ev1 = sEv[e * 3 + 1], ev2 = sEv[e * 3 + 2];
            float* vb = out_v + d * 3 * FF + tx * 8;
            red_add_v4(vb,
                       fmaf(xd[0], gs[0], ev0 * ge[0]), fmaf(xd[1], gs[1], ev0 * ge[1]),
                       fmaf(xd[2], gs[2], ev0 * ge[2]), fmaf(xd[3], gs[3], ev0 * ge[3]));
            red_add_v4(vb + 4,
                       fmaf(xd[4], gs[4], ev0 * ge[4]), fmaf(xd[5], gs[5], ev0 * ge[5]),
                       fmaf(xd[6], gs[6], ev0 * ge[6]), fmaf(xd[7], gs[7], ev0 * ge[7]));
            red_add_v4(vb + FF,
                       fmaf(xd[0], gs[0], ev1 * ge[0]), fmaf(xd[1], gs[1], ev1 * ge[1]),
                       fmaf(xd[2], gs[2], ev1 * ge[2]), fmaf(xd[3], gs[3], ev1 * ge[3]));
            red_add_v4(vb + FF + 4,
                       fmaf(xd[4], gs[4], ev1 * ge[4]), fmaf(xd[5], gs[5], ev1 * ge[5]),
                       fmaf(xd[6], gs[6], ev1 * ge[6]), fmaf(xd[7], gs[7], ev1 * ge[7]));
            red_add_v4(vb + 2 * FF,
                       fmaf(xd[0], gs[0], ev2 * ge[0]), fmaf(xd[1], gs[1], ev2 * ge[1]),
                       fmaf(xd[2], gs[2], ev2 * ge[2]), fmaf(xd[3], gs[3], ev2 * ge[3]));
            red_add_v4(vb + 2 * FF + 4,
                       fmaf(xd[4], gs[4], ev2 * ge[4]), fmaf(xd[5], gs[5], ev2 * ge[5]),
                       fmaf(xd[6], gs[6], ev2 * ge[6]), fmaf(xd[7], gs[7], ev2 * ge[7]));
        }
    }

    // ---- 4c) chunk 2: ms stats scatter ----
    tile_gemm256(sA, Ws2 + 512, 768, sW, tid, ty, tx, acc);
    {
        const float* bp = &bs2[512 + tx * 8];
        float4 b0 = *(const float4*)bp, b1 = *(const float4*)(bp + 4);
        float bb[8] = {b0.x, b0.y, b0.z, b0.w, b1.x, b1.y, b1.z, b1.w};
#pragma unroll
        for (int i = 0; i < 8; i++) {
            int e = ty * 8 + i;
            int d = sDst[e];
            float ff[8]; compute_frbf(sRbf, e, Wlin, 512 + tx * 8, ff);
            float ms[8];
#pragma unroll
            for (int j = 0; j < 8; j++) ms[j] = (acc[i][j] + bb[j]) * ff[j];
            int a = d * FF + tx * 8;
            red_add_v4(&g_sum[a],     ms[0], ms[1], ms[2], ms[3]);
            red_add_v4(&g_sum[a + 4], ms[4], ms[5], ms[6], ms[7]);
            red_add_v4(&g_sumsq[a],     ms[0] * ms[0], ms[1] * ms[1], ms[2] * ms[2], ms[3] * ms[3]);
            red_add_v4(&g_sumsq[a + 4], ms[4] * ms[4], ms[5] * ms[5], ms[6] * ms[6], ms[7] * ms[7]);
#pragma unroll
            for (int j = 0; j < 8; j++) {
                atomicMaxF(&g_maxb[a + j], ms[j]);
                atomicMinF(&g_minb[a + j], ms[j]);
            }
        }
    }
}

// ---------------- avg_log reduction (single block -> deterministic) ----------------
__global__ void avglog_kernel() {
    __shared__ float red[256];
    float s = 0.f;
    for (int i = threadIdx.x; i < NN; i += 256) s += log1pf(g_deg[i]);
    red[threadIdx.x] = s;
    __syncthreads();
    for (int off = 128; off > 0; off >>= 1) {
        if (threadIdx.x < off) red[threadIdx.x] += red[threadIdx.x + off];
        __syncthreads();
    }
    if (threadIdx.x == 0) g_avglog = red[0] / (float)NN;
}

// ---------------- build aggs (N x 12F) ----------------
__global__ void agg_kernel() {
    int idx = blockIdx.x * 256 + threadIdx.x;
    if (idx >= NN * FF) return;
    int n = idx >> 8;
    int c = idx & 255;
    float deg  = g_deg[n];
    float degc = fmaxf(deg, 1.f);
    float mean = g_sum[idx] / degc;
    float msq  = g_sumsq[idx] / degc;
    float stdv = sqrtf(fmaxf(msq - mean * mean, 0.f) + 1e-5f);
    float mn = (deg > 0.f) ? g_minb[idx] : 0.f;
    float mx = (deg > 0.f) ? g_maxb[idx] : 0.f;
    float avg  = g_avglog;
    float logd = log1pf(deg);
    float s1 = logd / avg;
    float s2 = avg / log1pf(degc);
    float* base = g_agg + n * (12 * FF) + c;
    base[0 * FF] = mean;      base[1 * FF] = mn;      base[2 * FF] = mx;      base[3 * FF] = stdv;
    base[4 * FF] = mean * s1; base[5 * FF] = mn * s1; base[6 * FF] = mx * s1; base[7 * FF] = stdv * s1;
    base[8 * FF] = mean * s2; base[9 * FF] = mn * s2; base[10 * FF] = mx * s2; base[11 * FF] = stdv * s2;
}

// ---------------- node post GEMM: out_x = x + [x|aggs] @ W_post + b_post ----------------
__global__ __launch_bounds__(256) void gemm_post_kernel(const float* __restrict__ x,
                                                        const float* __restrict__ Wpost,
                                                        const float* __restrict__ bpost,
                                                        float* __restrict__ out_x) {
    __shared__ float sA[64 * 16];
    __shared__ float sW[16 * 256];
    int tid = threadIdx.x, ty = tid >> 5, tx = tid & 31;
    int n0 = blockIdx.x * 64;
    float acc[8][8];
#pragma unroll
    for (int i = 0; i < 8; i++)
#pragma unroll
        for (int j = 0; j < 8; j++) acc[i][j] = 0.f;

    for (int k0 = 0; k0 < 13 * FF; k0 += 16) {
        const float* Asrc; int astr, aoff;
        if (k0 < FF) { Asrc = x; astr = FF; aoff = k0; }
        else         { Asrc = g_agg; astr = 12 * FF; aoff = k0 - FF; }
        {
            int vrow = tid >> 2, c4 = tid & 3;
            int n = n0 + vrow;
            float4 av = make_float4(0.f, 0.f, 0.f, 0.f);
            if (n < NN) av = *(const float4*)&Asrc[n * astr + aoff + c4 * 4];
            *(float4*)&sA[vrow * 16 + c4 * 4] = av;
        }
#pragma unroll
        for (int q = 0; q < 4; q++) {
            int v = q * 256 + tid, row = v >> 6, c4 = v & 63;
            *(float4*)&sW[row * 256 + c4 * 4] = *(const float4*)&Wpost[(k0 + row) * FF + c4 * 4];
        }
        __syncthreads();
#pragma unroll
        for (int kk4 = 0; kk4 < 4; kk4++) {
            float4 a4[8];
#pragma unroll
            for (int i = 0; i < 8; i++) a4[i] = *(const float4*)&sA[(ty * 8 + i) * 16 + kk4 * 4];
#pragma unroll
            for (int u = 0; u < 4; u++) {
                const float* wr = &sW[(kk4 * 4 + u) * 256 + tx * 8];
                float4 b0 = *(const float4*)wr, b1 = *(const float4*)(wr + 4);
                float bb[8] = {b0.x, b0.y, b0.z, b0.w, b1.x, b1.y, b1.z, b1.w};
#pragma unroll
                for (int i = 0; i < 8; i++) {
                    float a = (u == 0) ? a4[i].x : (u == 1) ? a4[i].y : (u == 2) ? a4[i].z : a4[i].w;
#pragma unroll
                    for (int j = 0; j < 8; j++) acc[i][j] = fmaf(a, bb[j], acc[i][j]);
                }
            }
        }
        __syncthreads();
    }
#pragma unroll
    for (int i = 0; i < 8; i++) {
        int n = n0 + ty * 8 + i;
        if (n < NN) {
#pragma unroll
            for (int j = 0; j < 8; j++) {
                int c = tx * 8 + j;
                out_x[n * FF + c] = x[n * FF + c] + acc[i][j] + bpost[c];
            }
        }
    }
}

// ---------------- launch ----------------
extern "C" void kernel_launch(void* const* d_in, const int* in_sizes, int n_in,
                              void* d_out, int out_size) {
    const float* x        = (const float*)d_in[0];
    const float* v        = (const float*)d_in[1];
    const float* edge_rbf = (const float*)d_in[2];
    const float* edge_vec = (const float*)d_in[3];
    const float* Wemb     = (const float*)d_in[4];
    const float* bemb     = (const float*)d_in[5];
    const float* Wpre     = (const float*)d_in[6];
    const float* bpre     = (const float*)d_in[7];
    const float* Ws1      = (const float*)d_in[8];
    const float* bs1      = (const float*)d_in[9];
    const float* Ws2      = (const float*)d_in[10];
    const float* bs2      = (const float*)d_in[11];
    const float* Wlin     = (const float*)d_in[12];
    const float* Wpost    = (const float*)d_in[13];
    const float* bpost    = (const float*)d_in[14];
    const int*   eidx     = (const int*)d_in[15];

    float* out_x = (float*)d_out;
    float* out_v = out_x + (size_t)NN * FF;

    cudaFuncSetAttribute(edge_kernel, cudaFuncAttributeMaxDynamicSharedMemorySize,
                         EDGE_SMEM_BYTES);

    // out_v starts as v; edge kernel atomically accumulates delta_v into it.
    cudaMemcpyAsync(out_v, v, (size_t)NN * 3 * FF * sizeof(float), cudaMemcpyDeviceToDevice);

    init_kernel<<<(NN * FF + 255) / 256, 256>>>();
    gemm_pre_kernel<<<dim3((NN + 63) / 64, 2), 256>>>(x, Wpre);
    edge_kernel<<<EE / TE, 256, EDGE_SMEM_BYTES>>>(x, edge_rbf, edge_vec,
                                                   Wemb, bemb, Wpre + 512 * FF, bpre,
                                                   Ws1, bs1, Ws2, bs2, Wlin, eidx, out_v);
    avglog_kernel<<<1, 256>>>();
    agg_kernel<<<(NN * FF + 255) / 256, 256>>>();
    gemm_post_kernel<<<(NN + 63) / 64, 256>>>(x, Wpost, bpost, out_x);
}

// round 6
// speedup vs baseline: 2.5668x; 2.5668x over previous
#include <cuda_runtime.h>
#include <math.h>
#include <stdint.h>

#define NN 10000
#define EE 160000
#define FF 256
#define RR 20
#define TE 64

// ---------------- device scratch ----------------
__device__ float g_P0[NN * FF];
__device__ float g_P1[NN * FF];
__device__ float g_sum[NN * FF];
__device__ float g_sumsq[NN * FF];
__device__ float g_minb[NN * FF];
__device__ float g_maxb[NN * FF];
__device__ float g_deg[NN];
__device__ float g_avglog;
__device__ float g_cat[NN * 3328];          // [x | aggs], tf32-rounded
// tf32-rounded weight copies
__device__ float g_Wemb[RR * FF];
__device__ float g_Wpre2[FF * FF];
__device__ float g_Ws1[FF * FF];
__device__ float g_Ws2[FF * 3 * FF];
__device__ float g_Wlin[RR * 3 * FF];
__device__ float g_Wpost[3328 * FF];

// ---------------- helpers ----------------
__device__ __forceinline__ float tf32r(float x) {
    uint32_t u;
    asm("cvt.rna.tf32.f32 %0, %1;" : "=r"(u) : "f"(x));
    return __uint_as_float(u);
}
__device__ __forceinline__ uint32_t F2U(float f) { return __float_as_uint(f); }

__device__ __forceinline__ void mma8(float c[4], uint32_t a0, uint32_t a1, uint32_t a2,
                                     uint32_t a3, uint32_t b0, uint32_t b1) {
    asm volatile(
        "mma.sync.aligned.m16n8k8.row.col.f32.tf32.tf32.f32 "
        "{%0,%1,%2,%3},{%4,%5,%6,%7},{%8,%9},{%0,%1,%2,%3};"
        : "+f"(c[0]), "+f"(c[1]), "+f"(c[2]), "+f"(c[3])
        : "r"(a0), "r"(a1), "r"(a2), "r"(a3), "r"(b0), "r"(b1));
}

__device__ __forceinline__ void cp16(uint32_t saddr, const void* g) {
    asm volatile("cp.async.ca.shared.global [%0], [%1], 16;" :: "r"(saddr), "l"(g));
}
__device__ __forceinline__ void cp_commit() { asm volatile("cp.async.commit_group;"); }
__device__ __forceinline__ void cp_wait1()  { asm volatile("cp.async.wait_group 1;"); }
__device__ __forceinline__ void cp_wait0()  { asm volatile("cp.async.wait_group 0;"); }

__device__ __forceinline__ void red_add_v2(float* p, float a, float b) {
    asm volatile("red.global.add.v2.f32 [%0], {%1,%2};" :: "l"(p), "f"(a), "f"(b) : "memory");
}
__device__ __forceinline__ void atomicMaxF(float* p, float v) {
    if (v >= 0.f) atomicMax((int*)p, __float_as_int(v));
    else          atomicMin((unsigned int*)p, __float_as_uint(v));
}
__device__ __forceinline__ void atomicMinF(float* p, float v) {
    if (v >= 0.f) atomicMin((int*)p, __float_as_int(v));
    else          atomicMax((unsigned int*)p, __float_as_uint(v));
}

// ---------------- weight conversion (once per launch; cheap) ----------------
__global__ void cvt_kernel(const float* __restrict__ Wemb, const float* __restrict__ Wpre,
                           const float* __restrict__ Ws1, const float* __restrict__ Ws2,
                           const float* __restrict__ Wlin, const float* __restrict__ Wpost) {
    int i = blockIdx.x * 256 + threadIdx.x;
    if (i < RR * FF)     g_Wemb[i]  = tf32r(Wemb[i]);
    if (i < FF * FF)   { g_Wpre2[i] = tf32r(Wpre[2 * FF * FF + i]); g_Ws1[i] = tf32r(Ws1[i]); }
    if (i < FF * 3 * FF) g_Ws2[i]   = tf32r(Ws2[i]);
    if (i < RR * 3 * FF) g_Wlin[i]  = tf32r(Wlin[i]);
    if (i < 3328 * FF)   g_Wpost[i] = tf32r(Wpost[i]);
}

// ---------------- init ----------------
__global__ void init_kernel(const float* __restrict__ x) {
    int i = blockIdx.x * 256 + threadIdx.x;
    if (i < NN * FF) {
        g_sum[i]   = 0.f;
        g_sumsq[i] = 0.f;
        g_minb[i]  = __int_as_float(0x7f800000);
        g_maxb[i]  = __int_as_float(0xff800000);
        int n = i >> 8, c = i & 255;
        g_cat[n * 3328 + c] = tf32r(x[i]);
        if (i < NN) g_deg[i] = 0.f;
    }
}

// ---------------- node precompute: P0/P1 (fp32 scalar; small) ----------------
__global__ __launch_bounds__(256) void gemm_pre_kernel(const float* __restrict__ x,
                                                       const float* __restrict__ Wpre) {
    __shared__ float sA[64 * 16];
    __shared__ float sW[16 * 256];
    const float* W = Wpre + blockIdx.y * FF * FF;
    float* P = blockIdx.y ? g_P1 : g_P0;
    int tid = threadIdx.x, ty = tid >> 5, tx = tid & 31;
    int n0 = blockIdx.x * 64;
    float acc[8][8];
#pragma unroll
    for (int i = 0; i < 8; i++)
#pragma unroll
        for (int j = 0; j < 8; j++) acc[i][j] = 0.f;

    for (int k0 = 0; k0 < FF; k0 += 16) {
        {
            int vrow = tid >> 2, c4 = tid & 3;
            int n = n0 + vrow;
            float4 av = make_float4(0.f, 0.f, 0.f, 0.f);
            if (n < NN) av = *(const float4*)&x[n * FF + k0 + c4 * 4];
            *(float4*)&sA[vrow * 16 + c4 * 4] = av;
        }
#pragma unroll
        for (int qq = 0; qq < 4; qq++) {
            int v = qq * 256 + tid, row = v >> 6, c4 = v & 63;
            *(float4*)&sW[row * 256 + c4 * 4] = *(const float4*)&W[(k0 + row) * FF + c4 * 4];
        }
        __syncthreads();
#pragma unroll
        for (int kk4 = 0; kk4 < 4; kk4++) {
            float4 a4[8];
#pragma unroll
            for (int i = 0; i < 8; i++) a4[i] = *(const float4*)&sA[(ty * 8 + i) * 16 + kk4 * 4];
#pragma unroll
            for (int u = 0; u < 4; u++) {
                const float* wr = &sW[(kk4 * 4 + u) * 256 + tx * 8];
                float4 b0 = *(const float4*)wr, b1 = *(const float4*)(wr + 4);
                float bb[8] = {b0.x, b0.y, b0.z, b0.w, b1.x, b1.y, b1.z, b1.w};
#pragma unroll
                for (int i = 0; i < 8; i++) {
                    float a = (u == 0) ? a4[i].x : (u == 1) ? a4[i].y : (u == 2) ? a4[i].z : a4[i].w;
#pragma unroll
                    for (int j = 0; j < 8; j++) acc[i][j] = fmaf(a, bb[j], acc[i][j]);
                }
            }
        }
        __syncthreads();
    }
#pragma unroll
    for (int i = 0; i < 8; i++) {
        int n = n0 + ty * 8 + i;
        if (n < NN) {
#pragma unroll
            for (int j = 0; j < 8; j++) P[n * FF + tx * 8 + j] = acc[i][j];
        }
    }
}

// ---------------- tf32 mma building blocks ----------------
// One k16 slab: A from smem (stride astr), B tile (16x256, stride 264) in sWb.
__device__ __forceinline__ void compute_k16(const float* sA, int astr, int arow0, int k0,
                                            const float* sWb, int lane, int col0,
                                            float acc[2][8][4]) {
    int q = lane >> 2, c = lane & 3;
#pragma unroll
    for (int ks = 0; ks < 16; ks += 8) {
        uint32_t a[2][4];
#pragma unroll
        for (int mt = 0; mt < 2; mt++) {
            const float* ap = sA + (arow0 + mt * 16 + q) * astr + k0 + ks + c;
            a[mt][0] = F2U(ap[0]);
            a[mt][2] = F2U(ap[4]);
            a[mt][1] = F2U(ap[8 * astr]);
            a[mt][3] = F2U(ap[8 * astr + 4]);
        }
#pragma unroll
        for (int nt = 0; nt < 8; nt++) {
            const float* bp = sWb + (ks + c) * 264 + col0 + nt * 8 + q;
            uint32_t b0 = F2U(bp[0]);
            uint32_t b1 = F2U(bp[4 * 264]);
            mma8(acc[0][nt], a[0][0], a[0][1], a[0][2], a[0][3], b0, b1);
            mma8(acc[1][nt], a[1][0], a[1][1], a[1][2], a[1][3], b0, b1);
        }
    }
}

// Full K=256 GEMM with double-buffered cp.async weight streaming.
__device__ __forceinline__ void mma_loop(const float* sA, int astr, float* sW, uint32_t sWu,
                                         const float* __restrict__ Wg, int wst,
                                         int tid, int lane, int arow0, int col0,
                                         float acc[2][8][4]) {
#pragma unroll
    for (int mt = 0; mt < 2; mt++)
#pragma unroll
        for (int nt = 0; nt < 8; nt++)
#pragma unroll
            for (int z = 0; z < 4; z++) acc[mt][nt][z] = 0.f;
    {
#pragma unroll
        for (int qq = 0; qq < 4; qq++) {
            int v = qq * 256 + tid, row = v >> 6, c4 = (v & 63) * 4;
            cp16(sWu + (uint32_t)((row * 264 + c4) * 4), Wg + row * wst + c4);
        }
        cp_commit();
    }
    for (int t = 0; t < 16; t++) {
        if (t + 1 < 16) {
            const float* src = Wg + (t + 1) * 16 * wst;
            uint32_t dbase = sWu + (uint32_t)((((t + 1) & 1) * 16 * 264) * 4);
#pragma unroll
            for (int qq = 0; qq < 4; qq++) {
                int v = qq * 256 + tid, row = v >> 6, c4 = (v & 63) * 4;
                cp16(dbase + (uint32_t)((row * 264 + c4) * 4), src + row * wst + c4);
            }
            cp_commit();
            cp_wait1();
        } else {
            cp_wait0();
        }
        __syncthreads();
        compute_k16(sA, astr, arow0, t * 16, sW + (t & 1) * 16 * 264, lane, col0, acc);
        __syncthreads();
    }
}

// K=24 (zero-padded K=20) mma: A = sRbfA (stride 28), B = sW rows 0..23.
__device__ __forceinline__ void fmma24(const float* sRbfA, const float* sW, int lane,
                                       int arow0, int col0, float facc[2][8][4]) {
#pragma unroll
    for (int mt = 0; mt < 2; mt++)
#pragma unroll
        for (int nt = 0; nt < 8; nt++)
#pragma unroll
            for (int z = 0; z < 4; z++) facc[mt][nt][z] = 0.f;
    int q = lane >> 2, c = lane & 3;
#pragma unroll
    for (int ks = 0; ks < 24; ks += 8) {
        uint32_t a[2][4];
#pragma unroll
        for (int mt = 0; mt < 2; mt++) {
            const float* ap = sRbfA + (arow0 + mt * 16 + q) * 28 + ks + c;
            a[mt][0] = F2U(ap[0]);
            a[mt][2] = F2U(ap[4]);
            a[mt][1] = F2U(ap[8 * 28]);
            a[mt][3] = F2U(ap[8 * 28 + 4]);
        }
#pragma unroll
        for (int nt = 0; nt < 8; nt++) {
            const float* bp = sW + (ks + c) * 264 + col0 + nt * 8 + q;
            uint32_t b0 = F2U(bp[0]);
            uint32_t b1 = F2U(bp[4 * 264]);
            mma8(facc[0][nt], a[0][0], a[0][1], a[0][2], a[0][3], b0, b1);
            mma8(facc[1][nt], a[1][0], a[1][1], a[1][2], a[1][3], b0, b1);
        }
    }
}

// ---------------- fused edge kernel ----------------
// smem floats: sA 64x260 | sM 64x260 | sW 2x16x264 | sRbfA 64x28 | sEv 192 | idx 128
#define EDGE_SMEM_FLOATS (16640 + 16640 + 8448 + 1792 + 192 + 128)
#define EDGE_SMEM_BYTES (EDGE_SMEM_FLOATS * 4)

__global__ __launch_bounds__(256, 1) void edge_kernel(
    const float* __restrict__ x, const float* __restrict__ edge_rbf,
    const float* __restrict__ edge_vec,
    const float* __restrict__ bemb, const float* __restrict__ bpre,
    const float* __restrict__ bs1, const float* __restrict__ bs2,
    const int* __restrict__ eidx, float* __restrict__ out_v) {
    extern __shared__ float sm[];
    float* sA    = sm;
    float* sM    = sm + 16640;
    float* sW    = sm + 33280;
    float* sRbfA = sm + 41728;
    float* sEv   = sm + 43520;
    int* sSrc = (int*)(sm + 43712);
    int* sDst = sSrc + 64;
    uint32_t sWu = (uint32_t)__cvta_generic_to_shared(sW);

    int tid = threadIdx.x, lane = tid & 31, w = tid >> 5;
    int arow0 = (w & 1) * 32, col0 = (w >> 1) * 64;
    int q = lane >> 2, cc = lane & 3;
    int e0 = blockIdx.x * TE;

    if (tid < TE) {
        int s = eidx[e0 + tid], d = eidx[EE + e0 + tid];
        sSrc[tid] = s; sDst[tid] = d;
        atomicAdd(&g_deg[d], 1.0f);
    }
    // rbf, tf32-rounded, padded to 24 cols (stride 28)
#pragma unroll
    for (int j = 0; j < 5; j++) {
        int i = tid + j * 256;
        int e = i / 20, k = i - e * 20;
        sRbfA[e * 28 + k] = tf32r(edge_rbf[(size_t)e0 * RR + i]);
    }
    { int e = tid >> 2, k = 20 + (tid & 3); sRbfA[e * 28 + k] = 0.f; }
    if (tid < 192) sEv[tid] = edge_vec[e0 * 3 + tid];
    // Wemb -> sW rows 0..19, zero rows 20..23
#pragma unroll
    for (int j = 0; j < 5; j++) {
        int v = tid + j * 256, row = v >> 6, c4 = (v & 63) * 4;
        *(float4*)&sW[row * 264 + c4] = *(const float4*)&g_Wemb[row * 256 + c4];
    }
    { int row = 20 + (tid >> 6), c4 = (tid & 63) * 4;
      *(float4*)&sW[row * 264 + c4] = make_float4(0.f, 0.f, 0.f, 0.f); }
    __syncthreads();

    // prefill sM = P0[src] + P1[dst] + bpre  (64 rows x 256 cols = 4096 float4s)
#pragma unroll
    for (int j = 0; j < 16; j++) {
        int f = (tid + j * 256) * 4;
        int r = f >> 8, c = f & 255;
        int s = sSrc[r], d = sDst[r];
        float4 p0 = *(const float4*)&g_P0[s * 256 + c];
        float4 p1 = *(const float4*)&g_P1[d * 256 + c];
        float4 bb = *(const float4*)&bpre[c];
        *(float4*)&sM[r * 260 + c] =
            make_float4(p0.x + p1.x + bb.x, p0.y + p1.y + bb.y,
                        p0.z + p1.z + bb.z, p0.w + p1.w + bb.w);
    }

    float acc[2][8][4];

    // ---- stage 1: sA = round(relu(rbf@Wemb + bemb)) ----
    fmma24(sRbfA, sW, lane, arow0, col0, acc);
    {
        float2 bias[8];
#pragma unroll
        for (int nt = 0; nt < 8; nt++) bias[nt] = *(const float2*)&bemb[col0 + nt * 8 + cc * 2];
#pragma unroll
        for (int mt = 0; mt < 2; mt++)
#pragma unroll
            for (int h = 0; h < 2; h++) {
                int r = arow0 + mt * 16 + q + h * 8;
#pragma unroll
                for (int nt = 0; nt < 8; nt++) {
                    int c = col0 + nt * 8 + cc * 2;
                    sA[r * 260 + c]     = tf32r(fmaxf(acc[mt][nt][h * 2 + 0] + bias[nt].x, 0.f));
                    sA[r * 260 + c + 1] = tf32r(fmaxf(acc[mt][nt][h * 2 + 1] + bias[nt].y, 0.f));
                }
            }
    }
    __syncthreads();

    // ---- stage 2: sM = round(sA@Wpre2 + sM) ----
    mma_loop(sA, 260, sW, sWu, g_Wpre2, 256, tid, lane, arow0, col0, acc);
#pragma unroll
    for (int mt = 0; mt < 2; mt++)
#pragma unroll
        for (int h = 0; h < 2; h++) {
            int r = arow0 + mt * 16 + q + h * 8;
#pragma unroll
            for (int nt = 0; nt < 8; nt++) {
                int c = col0 + nt * 8 + cc * 2;
                float* p = &sM[r * 260 + c];
                p[0] = tf32r(acc[mt][nt][h * 2 + 0] + p[0]);
                p[1] = tf32r(acc[mt][nt][h * 2 + 1] + p[1]);
            }
        }
    __syncthreads();

    // ---- stage 3: sA = round(silu(sM@Ws1 + bs1)) ----
    mma_loop(sM, 260, sW, sWu, g_Ws1, 256, tid, lane, arow0, col0, acc);
    {
        float2 bias[8];
#pragma unroll
        for (int nt = 0; nt < 8; nt++) bias[nt] = *(const float2*)&bs1[col0 + nt * 8 + cc * 2];
#pragma unroll
        for (int mt = 0; mt < 2; mt++)
#pragma unroll
            for (int h = 0; h < 2; h++) {
                int r = arow0 + mt * 16 + q + h * 8;
#pragma unroll
                for (int nt = 0; nt < 8; nt++) {
                    int c = col0 + nt * 8 + cc * 2;
                    float m0 = acc[mt][nt][h * 2 + 0] + bias[nt].x;
                    float m1 = acc[mt][nt][h * 2 + 1] + bias[nt].y;
                    sA[r * 260 + c]     = tf32r(__fdividef(m0, 1.f + __expf(-m0)));
                    sA[r * 260 + c + 1] = tf32r(__fdividef(m1, 1.f + __expf(-m1)));
                }
            }
    }
    __syncthreads();

    // ---- stage 4: three 256-col chunks of Ws2, fused with f = rbf@Wlin ----
    for (int ch = 0; ch < 3; ch++) {
        mma_loop(sA, 260, sW, sWu, g_Ws2 + ch * 256, 768, tid, lane, arow0, col0, acc);
        // load Wlin chunk into sW rows 0..19, zero rows 20..23
#pragma unroll
        for (int j = 0; j < 5; j++) {
            int v = tid + j * 256, row = v >> 6, c4 = (v & 63) * 4;
            *(float4*)&sW[row * 264 + c4] = *(const float4*)&g_Wlin[row * 768 + ch * 256 + c4];
        }
        { int row = 20 + (tid >> 6), c4 = (tid & 63) * 4;
          *(float4*)&sW[row * 264 + c4] = make_float4(0.f, 0.f, 0.f, 0.f); }
        __syncthreads();
        float facc[2][8][4];
        fmma24(sRbfA, sW, lane, arow0, col0, facc);
        float2 bias[8];
#pragma unroll
        for (int nt = 0; nt < 8; nt++)
            bias[nt] = *(const float2*)&bs2[ch * 256 + col0 + nt * 8 + cc * 2];

        if (ch == 0) {
            // g_state -> sM
#pragma unroll
            for (int mt = 0; mt < 2; mt++)
#pragma unroll
                for (int h = 0; h < 2; h++) {
                    int r = arow0 + mt * 16 + q + h * 8;
#pragma unroll
                    for (int nt = 0; nt < 8; nt++) {
                        int c = col0 + nt * 8 + cc * 2;
                        sM[r * 260 + c]     = (acc[mt][nt][h * 2 + 0] + bias[nt].x) * facc[mt][nt][h * 2 + 0];
                        sM[r * 260 + c + 1] = (acc[mt][nt][h * 2 + 1] + bias[nt].y) * facc[mt][nt][h * 2 + 1];
                    }
                }
        } else if (ch == 1) {
            // g_edge; mv scatter
#pragma unroll
            for (int mt = 0; mt < 2; mt++)
#pragma unroll
                for (int h = 0; h < 2; h++) {
                    int r = arow0 + mt * 16 + q + h * 8;
                    int d = sDst[r];
                    const float* xp = &x[(size_t)d * 256];
                    float ev0 = sEv[r * 3 + 0], ev1 = sEv[r * 3 + 1], ev2 = sEv[r * 3 + 2];
                    float* vbase = out_v + (size_t)d * 768;
#pragma unroll
                    for (int nt = 0; nt < 8; nt++) {
                        int c = col0 + nt * 8 + cc * 2;
                        float g0 = (acc[mt][nt][h * 2 + 0] + bias[nt].x) * facc[mt][nt][h * 2 + 0];
                        float g1 = (acc[mt][nt][h * 2 + 1] + bias[nt].y) * facc[mt][nt][h * 2 + 1];
                        float s0 = sM[r * 260 + c], s1 = sM[r * 260 + c + 1];
                        float2 xv = *(const float2*)&xp[c];
                        red_add_v2(vbase + c,       fmaf(xv.x, s0, ev0 * g0), fmaf(xv.y, s1, ev0 * g1));
                        red_add_v2(vbase + 256 + c, fmaf(xv.x, s0, ev1 * g0), fmaf(xv.y, s1, ev1 * g1));
                        red_add_v2(vbase + 512 + c, fmaf(xv.x, s0, ev2 * g0), fmaf(xv.y, s1, ev2 * g1));
                    }
                }
        } else {
            // ms stats scatter
#pragma unroll
            for (int mt = 0; mt < 2; mt++)
#pragma unroll
                for (int h = 0; h < 2; h++) {
                    int r = arow0 + mt * 16 + q + h * 8;
                    int d = sDst[r];
                    int base = d * 256;
#pragma unroll
                    for (int nt = 0; nt < 8; nt++) {
                        int c = col0 + nt * 8 + cc * 2;
                        float m0 = (acc[mt][nt][h * 2 + 0] + bias[nt].x) * facc[mt][nt][h * 2 + 0];
                        float m1 = (acc[mt][nt][h * 2 + 1] + bias[nt].y) * facc[mt][nt][h * 2 + 1];
                        red_add_v2(&g_sum[base + c],   m0,      m1);
                        red_add_v2(&g_sumsq[base + c], m0 * m0, m1 * m1);
                        atomicMaxF(&g_maxb[base + c],     m0);
                        atomicMaxF(&g_maxb[base + c + 1], m1);
                        atomicMinF(&g_minb[base + c],     m0);
                        atomicMinF(&g_minb[base + c + 1], m1);
                    }
                }
        }
        __syncthreads();
    }
}

// ---------------- avg_log ----------------
__global__ void avglog_kernel() {
    __shared__ float red[256];
    float s = 0.f;
    for (int i = threadIdx.x; i < NN; i += 256) s += log1pf(g_deg[i]);
    red[threadIdx.x] = s;
    __syncthreads();
    for (int off = 128; off > 0; off >>= 1) {
        if (threadIdx.x < off) red[threadIdx.x] += red[threadIdx.x + off];
        __syncthreads();
    }
    if (threadIdx.x == 0) g_avglog = red[0] / (float)NN;
}

// ---------------- aggs -> g_cat (rounded) ----------------
__global__ void agg_kernel() {
    int idx = blockIdx.x * 256 + threadIdx.x;
    if (idx >= NN * FF) return;
    int n = idx >> 8;
    int c = idx & 255;
    float deg  = g_deg[n];
    float degc = fmaxf(deg, 1.f);
    float mean = g_sum[idx] / degc;
    float msq  = g_sumsq[idx] / degc;
    float stdv = sqrtf(fmaxf(msq - mean * mean, 0.f) + 1e-5f);
    float mn = (deg > 0.f) ? g_minb[idx] : 0.f;
    float mx = (deg > 0.f) ? g_maxb[idx] : 0.f;
    float avg  = g_avglog;
    float logd = log1pf(deg);
    float s1 = logd / avg;
    float s2 = avg / log1pf(degc);
    float* base = g_cat + (size_t)n * 3328 + 256 + c;
    base[0 * FF]  = tf32r(mean);      base[1 * FF]  = tf32r(mn);
    base[2 * FF]  = tf32r(mx);        base[3 * FF]  = tf32r(stdv);
    base[4 * FF]  = tf32r(mean * s1); base[5 * FF]  = tf32r(mn * s1);
    base[6 * FF]  = tf32r(mx * s1);   base[7 * FF]  = tf32r(stdv * s1);
    base[8 * FF]  = tf32r(mean * s2); base[9 * FF]  = tf32r(mn * s2);
    base[10 * FF] = tf32r(mx * s2);   base[11 * FF] = tf32r(stdv * s2);
}

// ---------------- post GEMM: out_x = x + g_cat @ Wpost + bpost (tf32 mma) ----------------
__global__ __launch_bounds__(256) void gemm_post_kernel(const float* __restrict__ x,
                                                        const float* __restrict__ bpost,
                                                        float* __restrict__ out_x) {
    __shared__ float sW[2 * 16 * 264];
    __shared__ float sAt[2 * 64 * 20];
    uint32_t sWu = (uint32_t)__cvta_generic_to_shared(sW);
    uint32_t sAu = (uint32_t)__cvta_generic_to_shared(sAt);

    int tid = threadIdx.x, lane = tid & 31, w = tid >> 5;
    int arow0 = (w & 1) * 32, col0 = (w >> 1) * 64;
    int q = lane >> 2, cc = lane & 3;
    int n0 = blockIdx.x * 64;

    float acc[2][8][4];
#pragma unroll
    for (int mt = 0; mt < 2; mt++)
#pragma unroll
        for (int nt = 0; nt < 8; nt++)
#pragma unroll
            for (int z = 0; z < 4; z++) acc[mt][nt][z] = 0.f;

    // A-tile loader indices
    int arow = tid >> 2, ac4 = (tid & 3) * 4;
    int asrc_n = min(n0 + arow, NN - 1);

    // issue tile 0
    {
#pragma unroll
        for (int qq = 0; qq < 4; qq++) {
            int v = qq * 256 + tid, row = v >> 6, c4 = (v & 63) * 4;
            cp16(sWu + (uint32_t)((row * 264 + c4) * 4), g_Wpost + row * 256 + c4);
        }
        cp16(sAu + (uint32_t)((arow * 20 + ac4) * 4), g_cat + (size_t)asrc_n * 3328 + ac4);
        cp_commit();
    }
    const int KT = 3328 / 16;  // 208
    for (int t = 0; t < KT; t++) {
        if (t + 1 < KT) {
            int k0 = (t + 1) * 16;
            const float* wsrc = g_Wpost + (size_t)k0 * 256;
            uint32_t wb = sWu + (uint32_t)((((t + 1) & 1) * 16 * 264) * 4);
            uint32_t ab = sAu + (uint32_t)((((t + 1) & 1) * 64 * 20) * 4);
#pragma unroll
            for (int qq = 0; qq < 4; qq++) {
                int v = qq * 256 + tid, row = v >> 6, c4 = (v & 63) * 4;
                cp16(wb + (uint32_t)((row * 264 + c4) * 4), wsrc + row * 256 + c4);
            }
            cp16(ab + (uint32_t)((arow * 20 + ac4) * 4),
                 g_cat + (size_t)asrc_n * 3328 + k0 + ac4);
            cp_commit();
            cp_wait1();
        } else {
            cp_wait0();
        }
        __syncthreads();
        compute_k16(sAt + (t & 1) * 64 * 20, 20, arow0, 0, sW + (t & 1) * 16 * 264,
                    lane, col0, acc);
        __syncthreads();
    }

    // epilogue
#pragma unroll
    for (int mt = 0; mt < 2; mt++)
#pragma unroll
        for (int h = 0; h < 2; h++) {
            int r = arow0 + mt * 16 + q + h * 8;
            int n = n0 + r;
            if (n < NN) {
#pragma unroll
                for (int nt = 0; nt < 8; nt++) {
                    int c = col0 + nt * 8 + cc * 2;
                    float2 xv = *(const float2*)&x[(size_t)n * 256 + c];
                    float2 bb = *(const float2*)&bpost[c];
                    float2 o;
                    o.x = xv.x + acc[mt][nt][h * 2 + 0] + bb.x;
                    o.y = xv.y + acc[mt][nt][h * 2 + 1] + bb.y;
                    *(float2*)&out_x[(size_t)n * 256 + c] = o;
                }
            }
        }
}

// ---------------- launch ----------------
extern "C" void kernel_launch(void* const* d_in, const int* in_sizes, int n_in,
                              void* d_out, int out_size) {
    const float* x        = (const float*)d_in[0];
    const float* v        = (const float*)d_in[1];
    const float* edge_rbf = (const float*)d_in[2];
    const float* edge_vec = (const float*)d_in[3];
    const float* Wemb     = (const float*)d_in[4];
    const float* bemb     = (const float*)d_in[5];
    const float* Wpre     = (const float*)d_in[6];
    const float* bpre     = (const float*)d_in[7];
    const float* Ws1      = (const float*)d_in[8];
    const float* bs1      = (const float*)d_in[9];
    const float* Ws2      = (const float*)d_in[10];
    const float* bs2      = (const float*)d_in[11];
    const float* Wlin     = (const float*)d_in[12];
    const float* Wpost    = (const float*)d_in[13];
    const float* bpost    = (const float*)d_in[14];
    const int*   eidx     = (const int*)d_in[15];

    float* out_x = (float*)d_out;
    float* out_v = out_x + (size_t)NN * FF;

    cudaFuncSetAttribute(edge_kernel, cudaFuncAttributeMaxDynamicSharedMemorySize,
                         EDGE_SMEM_BYTES);

    cudaMemcpyAsync(out_v, v, (size_t)NN * 3 * FF * sizeof(float), cudaMemcpyDeviceToDevice);

    cvt_kernel<<<(3328 * FF + 255) / 256, 256>>>(Wemb, Wpre, Ws1, Ws2, Wlin, Wpost);
    init_kernel<<<(NN * FF + 255) / 256, 256>>>(x);
    gemm_pre_kernel<<<dim3((NN + 63) / 64, 2), 256>>>(x, Wpre);
    edge_kernel<<<EE / TE, 256, EDGE_SMEM_BYTES>>>(x, edge_rbf, edge_vec,
                                                   bemb, bpre, bs1, bs2, eidx, out_v);
    avglog_kernel<<<1, 256>>>();
    agg_kernel<<<(NN * FF + 255) / 256, 256>>>();
    gemm_post_kernel<<<(NN + 63) / 64, 256>>>(x, bpost, out_x);
}